// round 2
// baseline (speedup 1.0000x reference)
#include <cuda_runtime.h>
#include <cuda_bf16.h>

// Problem constants
#define BB   64
#define SS   1024
#define II   512
#define HH   512
#define NG3  1536          // 3*H
#define STEPN 4608         // [Wh1 | Wi2 | Wh2] columns
#define NCTA  144          // persistent CTAs (<= 148 SMs, 1 per SM)
#define ASTR  520          // A smem stride (words); 520 % 32 == 8 -> conflict-free frags
#define BSTR  40           // B smem stride (words); 40 % 32 == 8  -> conflict-free frags
#define SCAN_SMEM ((64 * ASTR + 512 * BSTR) * 4)   // 215040 bytes

// ---------------- static device scratch (no allocations allowed) -------------
__device__ float g_xs1[(long)SS * BB * NG3];   // layer-1 input projections [s][b][3H]
__device__ float g_G[BB * STEPN];              // per-step GEMM results
__device__ float g_h[2][2][BB * HH];           // [pingpong][layer][b*H]
__device__ float g_gb1[BB * NG3];
__device__ float g_gb2[BB * NG3];
__device__ float g_h1b[BB * HH];
__device__ float g_fcin[BB * 2 * HH];          // [b][fwd H | bwd H]

__device__ unsigned g_cnt = 0;                 // grid barrier arrival count
__device__ unsigned g_gen = 0;                 // grid barrier generation

// ---------------- helpers ----------------------------------------------------
__device__ __forceinline__ unsigned f2tf(float f) {
    unsigned u;
    asm("cvt.rna.tf32.f32 %0, %1;" : "=r"(u) : "f"(f));
    return u;
}

__device__ __forceinline__ void mma8(float c[4], const unsigned a[4], unsigned b0, unsigned b1) {
    asm volatile(
        "mma.sync.aligned.m16n8k8.row.col.f32.tf32.tf32.f32 "
        "{%0,%1,%2,%3},{%4,%5,%6,%7},{%8,%9},{%0,%1,%2,%3};"
        : "+f"(c[0]), "+f"(c[1]), "+f"(c[2]), "+f"(c[3])
        : "r"(a[0]), "r"(a[1]), "r"(a[2]), "r"(a[3]), "r"(b0), "r"(b1));
}

__device__ __forceinline__ float sigm(float v) { return 1.f / (1.f + __expf(-v)); }

// release/acquire grid barrier (all NCTA CTAs co-resident by construction)
__device__ __forceinline__ void grid_bar() {
    __threadfence();          // publish this thread's global writes
    __syncthreads();
    if (threadIdx.x == 0) {
        unsigned gen;
        asm volatile("ld.acquire.gpu.u32 %0, [%1];" : "=r"(gen) : "l"(&g_gen) : "memory");
        if (atomicAdd(&g_cnt, 1) == NCTA - 1) {
            atomicExch(&g_cnt, 0);
            __threadfence();
            asm volatile("st.release.gpu.u32 [%0], %1;" :: "l"(&g_gen), "r"(gen + 1) : "memory");
        } else {
            unsigned cur;
            do {
                asm volatile("ld.acquire.gpu.u32 %0, [%1];" : "=r"(cur) : "l"(&g_gen) : "memory");
            } while (cur == gen);
        }
    }
    __syncthreads();
}

// ---------------- 64x64 TF32 GEMM core (128 threads, 4 warps 2x2) ------------
// (used by the non-scan kernels: proj / backward / fc)
__device__ __forceinline__ void gemm_core(const float* __restrict__ A, long lda,
                                          const float* __restrict__ B512, int K,
                                          const float* __restrict__ bias,
                                          float* __restrict__ C, int ldc)
{
    __shared__ unsigned As[64][33];
    __shared__ unsigned Bs[32][65];

    const int tid  = threadIdx.x;
    const int lane = tid & 31;
    const int warp = tid >> 5;
    const int wm = warp >> 1, wn = warp & 1;
    const int g = lane >> 2, t = lane & 3;

    float acc[2][4][4];
#pragma unroll
    for (int a = 0; a < 2; a++)
#pragma unroll
        for (int b = 0; b < 4; b++)
#pragma unroll
            for (int c = 0; c < 4; c++) acc[a][b][c] = 0.f;

    float4 ra[4], rbv[4];
#pragma unroll
    for (int i = 0; i < 4; i++) {
        int f = tid + i * 128;
        ra[i]  = *(const float4*)(A + (long)(f >> 3) * lda + ((f & 7) << 2));
        rbv[i] = *(const float4*)(B512 + (long)(f >> 4) * 512 + ((f & 15) << 2));
    }

    for (int kc = 0; kc < K; kc += 32) {
#pragma unroll
        for (int i = 0; i < 4; i++) {
            int f = tid + i * 128;
            int r = f >> 3, cc = (f & 7) << 2;
            As[r][cc + 0] = f2tf(ra[i].x);
            As[r][cc + 1] = f2tf(ra[i].y);
            As[r][cc + 2] = f2tf(ra[i].z);
            As[r][cc + 3] = f2tf(ra[i].w);
            int bk = f >> 4, bc = (f & 15) << 2;
            Bs[bk][bc + 0] = f2tf(rbv[i].x);
            Bs[bk][bc + 1] = f2tf(rbv[i].y);
            Bs[bk][bc + 2] = f2tf(rbv[i].z);
            Bs[bk][bc + 3] = f2tf(rbv[i].w);
        }
        __syncthreads();

        if (kc + 32 < K) {
#pragma unroll
            for (int i = 0; i < 4; i++) {
                int f = tid + i * 128;
                ra[i]  = *(const float4*)(A + (long)(f >> 3) * lda + (kc + 32) + ((f & 7) << 2));
                rbv[i] = *(const float4*)(B512 + (long)(kc + 32 + (f >> 4)) * 512 + ((f & 15) << 2));
            }
        }

#pragma unroll
        for (int ks = 0; ks < 4; ks++) {
            int kb = ks * 8;
            unsigned afr[2][4];
#pragma unroll
            for (int mf = 0; mf < 2; mf++) {
                int rb_ = wm * 32 + mf * 16;
                afr[mf][0] = As[rb_ + g][kb + t];
                afr[mf][1] = As[rb_ + 8 + g][kb + t];
                afr[mf][2] = As[rb_ + g][kb + 4 + t];
                afr[mf][3] = As[rb_ + 8 + g][kb + 4 + t];
            }
#pragma unroll
            for (int nf = 0; nf < 4; nf++) {
                int cb = wn * 32 + nf * 8;
                unsigned b0 = Bs[kb + t][cb + g];
                unsigned b1 = Bs[kb + 4 + t][cb + g];
                mma8(acc[0][nf], afr[0], b0, b1);
                mma8(acc[1][nf], afr[1], b0, b1);
            }
        }
        __syncthreads();
    }

#pragma unroll
    for (int mf = 0; mf < 2; mf++)
#pragma unroll
        for (int nf = 0; nf < 4; nf++) {
            int row = wm * 32 + mf * 16 + g;
            int col = wn * 32 + nf * 8 + t * 2;
            float b0v = bias ? bias[col] : 0.f;
            float b1v = bias ? bias[col + 1] : 0.f;
            C[(long)row * ldc + col]           = acc[mf][nf][0] + b0v;
            C[(long)row * ldc + col + 1]       = acc[mf][nf][1] + b1v;
            C[(long)(row + 8) * ldc + col]     = acc[mf][nf][2] + b0v;
            C[(long)(row + 8) * ldc + col + 1] = acc[mf][nf][3] + b1v;
        }
}

// ---------------- kernels -----------------------------------------------------

__global__ void k_zero() {
    long n = 2L * 2 * BB * HH;
    float* p = &g_h[0][0][0];
    for (long i = blockIdx.x * blockDim.x + threadIdx.x; i < n; i += (long)gridDim.x * blockDim.x)
        p[i] = 0.f;
}

// xs1[s][b][n] = x[b][s][:] @ Wi[0][0][gate] + b[0][0]
__global__ __launch_bounds__(128) void k_proj(const float* __restrict__ x,
                                              const float* __restrict__ Wi,
                                              const float* __restrict__ bv)
{
    int n = blockIdx.x * 64;
    int s = blockIdx.y;
    int gate = n >> 9, cig = n & 511;
    const float* A = x + (long)s * II;
    const float* B512 = Wi + ((long)(0 * 3 + gate)) * 512 * 512 + cig;   // Wi[0][0]
    gemm_core(A, (long)SS * II, B512, 512, bv + n,
              g_xs1 + ((long)s * BB) * NG3 + n, NG3);
}

// ---------------- persistent scan kernel --------------------------------------
// 144 CTAs, each owns a 64x32 tile of the fused step GEMM
// cols [0,1536)=h1@Wh1 ; [1536,3072)=h1@Wi2 ; [3072,4608)=h2@Wh2
__global__ void __launch_bounds__(128, 1) k_scan(const float* __restrict__ Wi,
                                                 const float* __restrict__ Wh,
                                                 const float* __restrict__ bv)
{
    extern __shared__ unsigned smemu[];
    unsigned* As = smemu;                 // 64 x ASTR
    unsigned* Bs = smemu + 64 * ASTR;     // 512 x BSTR

    const int tid  = threadIdx.x;
    const int lane = tid & 31;
    const int warp = tid >> 5;
    const int wm = warp >> 1, wn = warp & 1;
    const int gq = lane >> 2, tq = lane & 3;
    const int ct = blockIdx.x;
    const int seg = ct / 48;
    const int c0  = (ct * 32) % NG3;
    const int gate = c0 >> 9, cig = c0 & 511;

    const float* Wsrc;
    if (seg == 0)      Wsrc = Wh + (long)gate * 262144 + cig;        // Wh[0][0]
    else if (seg == 1) Wsrc = Wi + (long)(6 + gate) * 262144 + cig;  // Wi[1][0]
    else               Wsrc = Wh + (long)(6 + gate) * 262144 + cig;  // Wh[1][0]

    // one-time weight stage: global -> TF32 -> smem (resident for all steps)
#pragma unroll 4
    for (int i = 0; i < 32; i++) {
        int f = tid + i * 128;
        int kk = f >> 3, c4 = (f & 7) << 2;
        float4 w = *(const float4*)(Wsrc + (long)kk * 512 + c4);
        uint4 u;
        u.x = f2tf(w.x); u.y = f2tf(w.y); u.z = f2tf(w.z); u.w = f2tf(w.w);
        *(uint4*)(Bs + kk * BSTR + c4) = u;
    }
    __syncthreads();

    const float* b2 = bv + 2 * NG3;   // b[1][0]

    for (int k = 0; k <= SS; k++) {
        const int rd = k & 1, wr = rd ^ 1;

        // stage A (current h) into smem as TF32
        const float4* h4 = (const float4*)((seg == 2) ? g_h[rd][1] : g_h[rd][0]);
#pragma unroll 4
        for (int i = 0; i < 64; i++) {
            int f = tid + i * 128;
            float4 v = h4[f];
            uint4 u;
            u.x = f2tf(v.x); u.y = f2tf(v.y); u.z = f2tf(v.z); u.w = f2tf(v.w);
            *(uint4*)(As + (f >> 7) * ASTR + ((f & 127) << 2)) = u;
        }
        __syncthreads();

        // 64x32 tile, K=512
        float acc[2][2][4];
#pragma unroll
        for (int a = 0; a < 2; a++)
#pragma unroll
            for (int b = 0; b < 2; b++)
#pragma unroll
                for (int c = 0; c < 4; c++) acc[a][b][c] = 0.f;

        const unsigned* ApA = As + (wm * 32 + gq) * ASTR;
        const unsigned* Bp0 = Bs + wn * 16 + gq;
        const unsigned* Bp1 = Bp0 + 8;

#pragma unroll 4
        for (int k8 = 0; k8 < 64; k8++) {
            const int kb = k8 * 8;
            unsigned a0[4], a1[4];
            a0[0] = ApA[kb + tq];
            a0[1] = ApA[8 * ASTR + kb + tq];
            a0[2] = ApA[kb + 4 + tq];
            a0[3] = ApA[8 * ASTR + kb + 4 + tq];
            a1[0] = ApA[16 * ASTR + kb + tq];
            a1[1] = ApA[24 * ASTR + kb + tq];
            a1[2] = ApA[16 * ASTR + kb + 4 + tq];
            a1[3] = ApA[24 * ASTR + kb + 4 + tq];
            unsigned b00 = Bp0[(kb + tq) * BSTR];
            unsigned b01 = Bp0[(kb + 4 + tq) * BSTR];
            unsigned b10 = Bp1[(kb + tq) * BSTR];
            unsigned b11 = Bp1[(kb + 4 + tq) * BSTR];
            mma8(acc[0][0], a0, b00, b01);
            mma8(acc[1][0], a1, b00, b01);
            mma8(acc[0][1], a0, b10, b11);
            mma8(acc[1][1], a1, b10, b11);
        }

        // write G tile
        {
            int colb = ct * 32 + wn * 16;
#pragma unroll
            for (int mf = 0; mf < 2; mf++)
#pragma unroll
                for (int nf = 0; nf < 2; nf++) {
                    int row = wm * 32 + mf * 16 + gq;
                    int col = colb + nf * 8 + tq * 2;
                    *(float2*)(g_G + (long)row * STEPN + col) =
                        make_float2(acc[mf][nf][0], acc[mf][nf][1]);
                    *(float2*)(g_G + (long)(row + 8) * STEPN + col) =
                        make_float2(acc[mf][nf][2], acc[mf][nf][3]);
                }
        }
        grid_bar();   // G visible everywhere

        // elementwise GRU updates (distributed over all threads)
        for (int it = ct * 128 + tid; it < 2 * BB * HH; it += NCTA * 128) {
            int half = it >> 15;          // 0: layer1, 1: layer2
            int b = (it >> 9) & 63;
            int u = it & 511;
            const float* G = g_G + b * STEPN;
            if (half == 0) {
                if (k < SS) {             // layer-1 step k
                    const float* xs = g_xs1 + ((long)k * BB + b) * NG3;
                    float r  = sigm(xs[u] + G[u]);
                    float z  = sigm(xs[512 + u] + G[512 + u]);
                    float nn = tanhf(xs[1024 + u] + r * G[1024 + u]);
                    float hp = g_h[rd][0][b * HH + u];
                    g_h[wr][0][b * HH + u] = (1.f - z) * nn + z * hp;
                }
            } else {
                if (k >= 1) {             // layer-2 step k-1
                    float xr = G[1536 + u] + b2[u];
                    float xz = G[2048 + u] + b2[512 + u];
                    float xn = G[2560 + u] + b2[1024 + u];
                    float r2 = sigm(xr + G[3072 + u]);
                    float z2 = sigm(xz + G[3584 + u]);
                    float n2 = tanhf(xn + r2 * G[4096 + u]);
                    float hp = g_h[rd][1][b * HH + u];
                    float v  = (1.f - z2) * n2 + z2 * hp;
                    g_h[wr][1][b * HH + u] = v;
                    if (k == SS) g_fcin[b * (2 * HH) + u] = v;
                }
            }
        }
        grid_bar();   // h visible everywhere before next step
    }
}

// backward step 1 projection: x[:,1023,:] @ Wi[0][1] + b[0][1]
__global__ __launch_bounds__(128) void k_gb1(const float* __restrict__ x,
                                             const float* __restrict__ Wi,
                                             const float* __restrict__ bv)
{
    int n = blockIdx.x * 64;
    int gate = n >> 9, cig = n & 511;
    const float* A = x + (long)(SS - 1) * II;
    const float* B512 = Wi + ((long)(1 * 3 + gate)) * 512 * 512 + cig;   // Wi[0][1]
    gemm_core(A, (long)SS * II, B512, 512, bv + 1 * NG3 + n, g_gb1 + n, NG3);
}

__global__ void k_ewb1()
{
    int b = blockIdx.x, u = threadIdx.x;
    float z  = sigm(g_gb1[b * NG3 + 512 + u]);
    float nn = tanhf(g_gb1[b * NG3 + 1024 + u]);
    g_h1b[b * HH + u] = (1.f - z) * nn;
}

// backward step 2 projection: h1b @ Wi[1][1] + b[1][1]
__global__ __launch_bounds__(128) void k_gb2(const float* __restrict__ Wi,
                                             const float* __restrict__ bv)
{
    int n = blockIdx.x * 64;
    int gate = n >> 9, cig = n & 511;
    const float* B512 = Wi + ((long)(3 * 3 + gate)) * 512 * 512 + cig;   // Wi[1][1]
    gemm_core(g_h1b, HH, B512, 512, bv + 3 * NG3 + n, g_gb2 + n, NG3);
}

__global__ void k_ewb2()
{
    int b = blockIdx.x, u = threadIdx.x;
    float z  = sigm(g_gb2[b * NG3 + 512 + u]);
    float nn = tanhf(g_gb2[b * NG3 + 1024 + u]);
    g_fcin[b * (2 * HH) + HH + u] = (1.f - z) * nn;
}

// final FC: out[64,512] = fcin[64,1024] @ fc_w + fc_b
__global__ __launch_bounds__(128) void k_fc(const float* __restrict__ fw,
                                            const float* __restrict__ fb,
                                            float* __restrict__ out)
{
    int n = blockIdx.x * 64;
    gemm_core(g_fcin, 2 * HH, fw + n, 2 * HH, fb + n, out + n, HH);
}

// ---------------- launch ------------------------------------------------------
extern "C" void kernel_launch(void* const* d_in, const int* in_sizes, int n_in,
                              void* d_out, int out_size)
{
    const float* x  = (const float*)d_in[0];
    const float* Wi = (const float*)d_in[1];
    const float* Wh = (const float*)d_in[2];
    const float* bv = (const float*)d_in[3];
    const float* fw = (const float*)d_in[4];
    const float* fb = (const float*)d_in[5];
    float* out = (float*)d_out;

    cudaFuncSetAttribute(k_scan, cudaFuncAttributeMaxDynamicSharedMemorySize, SCAN_SMEM);

    k_zero<<<64, 256>>>();

    dim3 gp(NG3 / 64, SS);
    k_proj<<<gp, 128>>>(x, Wi, bv);

    // backward direction: collapses to 2 GRU steps (h0 = 0)
    k_gb1<<<NG3 / 64, 128>>>(x, Wi, bv);
    k_ewb1<<<BB, HH>>>();
    k_gb2<<<NG3 / 64, 128>>>(Wi, bv);
    k_ewb2<<<BB, HH>>>();

    // forward scan: one persistent kernel, 1025 fused steps
    k_scan<<<NCTA, 128, SCAN_SMEM>>>(Wi, Wh, bv);

    k_fc<<<HH / 64, 128>>>(fw, fb, out);
}

// round 3
// speedup vs baseline: 1.4380x; 1.4380x over previous
#include <cuda_runtime.h>
#include <cuda_bf16.h>

// Problem constants
#define BB   64
#define SS   1024
#define II   512
#define HH   512
#define NG3  1536          // 3*H
#define STEPN 4608         // [Wh1 | Wi2 | Wh2] columns
#define NCTA  144          // persistent CTAs (1/SM guaranteed by smem)
#define ASTR  516          // A smem stride words; 516%32==4 -> conflict-free A frags
#define BSTR  40           // B smem stride words; conflict-free B frags
#define SCAN_SMEM ((64 * ASTR + 512 * BSTR) * 4)   // 214016 B
#define EWTOT (2 * BB * HH)                        // 65536 elementwise items
#define NTHR  (NCTA * 128)

// ---------------- static device scratch --------------------------------------
__device__ float g_xs1[(long)SS * BB * NG3];   // layer-1 input projections [s][b][3H]
__device__ float g_G[BB * STEPN];              // per-step GEMM results
__device__ float g_h[2][2][BB * HH];           // fp32 h   [pingpong][layer][b*H]
__device__ float g_ha[2][2][BB * HH];          // tf32-rounded h (A operand copy)
__device__ float g_gb1[BB * NG3];
__device__ float g_gb2[BB * NG3];
__device__ float g_h1b[BB * HH];
__device__ float g_fcin[BB * 2 * HH];          // [b][fwd H | bwd H]

__device__ unsigned g_cnt = 0;                 // grid barrier arrival count
__device__ unsigned g_gen = 0;                 // grid barrier generation

// ---------------- helpers ----------------------------------------------------
__device__ __forceinline__ unsigned f2tf(float f) {
    unsigned u;
    asm("cvt.rna.tf32.f32 %0, %1;" : "=r"(u) : "f"(f));
    return u;
}

__device__ __forceinline__ void mma8(float c[4], const unsigned a[4], unsigned b0, unsigned b1) {
    asm volatile(
        "mma.sync.aligned.m16n8k8.row.col.f32.tf32.tf32.f32 "
        "{%0,%1,%2,%3},{%4,%5,%6,%7},{%8,%9},{%0,%1,%2,%3};"
        : "+f"(c[0]), "+f"(c[1]), "+f"(c[2]), "+f"(c[3])
        : "r"(a[0]), "r"(a[1]), "r"(a[2]), "r"(a[3]), "r"(b0), "r"(b1));
}

__device__ __forceinline__ float sigm(float v) { return 1.f / (1.f + __expf(-v)); }
__device__ __forceinline__ float tanh_fast(float v) {
    return 1.f - 2.f / (1.f + __expf(2.f * v));
}

__device__ __forceinline__ void cpasync16(unsigned saddr, const void* g) {
    asm volatile("cp.async.cg.shared.global [%0], [%1], 16;" :: "r"(saddr), "l"(g));
}
__device__ __forceinline__ void cpasync_wait_all() {
    asm volatile("cp.async.commit_group;\n\tcp.async.wait_group 0;" ::: "memory");
}

// CG-style grid barrier: leader-only fence (cumulative), others rely on bar.sync
__device__ __forceinline__ void grid_bar() {
    __syncthreads();
    if (threadIdx.x == 0) {
        __threadfence();                       // cumulative: publishes whole CTA
        unsigned gen;
        asm volatile("ld.acquire.gpu.u32 %0, [%1];" : "=r"(gen) : "l"(&g_gen) : "memory");
        if (atomicAdd(&g_cnt, 1) == NCTA - 1) {
            atomicExch(&g_cnt, 0);
            asm volatile("st.release.gpu.u32 [%0], %1;" :: "l"(&g_gen), "r"(gen + 1) : "memory");
        } else {
            unsigned cur;
            do {
                asm volatile("ld.acquire.gpu.u32 %0, [%1];" : "=r"(cur) : "l"(&g_gen) : "memory");
            } while (cur == gen);
        }
    }
    __syncthreads();
}

// ---------------- 64x64 TF32 GEMM core (non-scan kernels) --------------------
__device__ __forceinline__ void gemm_core(const float* __restrict__ A, long lda,
                                          const float* __restrict__ B512, int K,
                                          const float* __restrict__ bias,
                                          float* __restrict__ C, int ldc)
{
    __shared__ unsigned As[64][33];
    __shared__ unsigned Bs[32][65];

    const int tid  = threadIdx.x;
    const int lane = tid & 31;
    const int warp = tid >> 5;
    const int wm = warp >> 1, wn = warp & 1;
    const int g = lane >> 2, t = lane & 3;

    float acc[2][4][4];
#pragma unroll
    for (int a = 0; a < 2; a++)
#pragma unroll
        for (int b = 0; b < 4; b++)
#pragma unroll
            for (int c = 0; c < 4; c++) acc[a][b][c] = 0.f;

    float4 ra[4], rbv[4];
#pragma unroll
    for (int i = 0; i < 4; i++) {
        int f = tid + i * 128;
        ra[i]  = *(const float4*)(A + (long)(f >> 3) * lda + ((f & 7) << 2));
        rbv[i] = *(const float4*)(B512 + (long)(f >> 4) * 512 + ((f & 15) << 2));
    }

    for (int kc = 0; kc < K; kc += 32) {
#pragma unroll
        for (int i = 0; i < 4; i++) {
            int f = tid + i * 128;
            int r = f >> 3, cc = (f & 7) << 2;
            As[r][cc + 0] = f2tf(ra[i].x);
            As[r][cc + 1] = f2tf(ra[i].y);
            As[r][cc + 2] = f2tf(ra[i].z);
            As[r][cc + 3] = f2tf(ra[i].w);
            int bk = f >> 4, bc = (f & 15) << 2;
            Bs[bk][bc + 0] = f2tf(rbv[i].x);
            Bs[bk][bc + 1] = f2tf(rbv[i].y);
            Bs[bk][bc + 2] = f2tf(rbv[i].z);
            Bs[bk][bc + 3] = f2tf(rbv[i].w);
        }
        __syncthreads();

        if (kc + 32 < K) {
#pragma unroll
            for (int i = 0; i < 4; i++) {
                int f = tid + i * 128;
                ra[i]  = *(const float4*)(A + (long)(f >> 3) * lda + (kc + 32) + ((f & 7) << 2));
                rbv[i] = *(const float4*)(B512 + (long)(kc + 32 + (f >> 4)) * 512 + ((f & 15) << 2));
            }
        }

#pragma unroll
        for (int ks = 0; ks < 4; ks++) {
            int kb = ks * 8;
            unsigned afr[2][4];
#pragma unroll
            for (int mf = 0; mf < 2; mf++) {
                int rb_ = wm * 32 + mf * 16;
                afr[mf][0] = As[rb_ + g][kb + t];
                afr[mf][1] = As[rb_ + 8 + g][kb + t];
                afr[mf][2] = As[rb_ + g][kb + 4 + t];
                afr[mf][3] = As[rb_ + 8 + g][kb + 4 + t];
            }
#pragma unroll
            for (int nf = 0; nf < 4; nf++) {
                int cb = wn * 32 + nf * 8;
                unsigned b0 = Bs[kb + t][cb + g];
                unsigned b1 = Bs[kb + 4 + t][cb + g];
                mma8(acc[0][nf], afr[0], b0, b1);
                mma8(acc[1][nf], afr[1], b0, b1);
            }
        }
        __syncthreads();
    }

#pragma unroll
    for (int mf = 0; mf < 2; mf++)
#pragma unroll
        for (int nf = 0; nf < 4; nf++) {
            int row = wm * 32 + mf * 16 + g;
            int col = wn * 32 + nf * 8 + t * 2;
            float b0v = bias ? bias[col] : 0.f;
            float b1v = bias ? bias[col + 1] : 0.f;
            C[(long)row * ldc + col]           = acc[mf][nf][0] + b0v;
            C[(long)row * ldc + col + 1]       = acc[mf][nf][1] + b1v;
            C[(long)(row + 8) * ldc + col]     = acc[mf][nf][2] + b0v;
            C[(long)(row + 8) * ldc + col + 1] = acc[mf][nf][3] + b1v;
        }
}

// ---------------- kernels -----------------------------------------------------

__global__ void k_zero() {
    long n = 2L * 2 * BB * HH;
    float* p = &g_h[0][0][0];
    float* q = &g_ha[0][0][0];
    for (long i = blockIdx.x * blockDim.x + threadIdx.x; i < n; i += (long)gridDim.x * blockDim.x) {
        p[i] = 0.f;
        q[i] = 0.f;
    }
}

// xs1[s][b][n] = x[b][s][:] @ Wi[0][0][gate] + b[0][0]
__global__ __launch_bounds__(128) void k_proj(const float* __restrict__ x,
                                              const float* __restrict__ Wi,
                                              const float* __restrict__ bv)
{
    int n = blockIdx.x * 64;
    int s = blockIdx.y;
    int gate = n >> 9, cig = n & 511;
    const float* A = x + (long)s * II;
    const float* B512 = Wi + ((long)(0 * 3 + gate)) * 512 * 512 + cig;   // Wi[0][0]
    gemm_core(A, (long)SS * II, B512, 512, bv + n,
              g_xs1 + ((long)s * BB) * NG3 + n, NG3);
}

// ---------------- persistent scan kernel --------------------------------------
// 144 CTAs, each owns a 64x32 tile of the fused step GEMM
// cols [0,1536)=h1@Wh1 ; [1536,3072)=h1@Wi2 ; [3072,4608)=h2@Wh2
__global__ void __launch_bounds__(128, 1) k_scan(const float* __restrict__ Wi,
                                                 const float* __restrict__ Wh,
                                                 const float* __restrict__ bv)
{
    extern __shared__ unsigned smemu[];
    unsigned* As = smemu;                 // 64 x ASTR
    unsigned* Bs = smemu + 64 * ASTR;     // 512 x BSTR

    const int tid  = threadIdx.x;
    const int lane = tid & 31;
    const int warp = tid >> 5;
    const int wm = warp >> 1, wn = warp & 1;
    const int gq = lane >> 2, tq = lane & 3;
    const int ct = blockIdx.x;
    const int seg = ct / 48;
    const int c0  = (ct * 32) % NG3;
    const int gate = c0 >> 9, cig = c0 & 511;

    const float* Wsrc;
    if (seg == 0)      Wsrc = Wh + (long)gate * 262144 + cig;        // Wh[0][0]
    else if (seg == 1) Wsrc = Wi + (long)(6 + gate) * 262144 + cig;  // Wi[1][0]
    else               Wsrc = Wh + (long)(6 + gate) * 262144 + cig;  // Wh[1][0]

    // one-time weight stage: global -> TF32 -> smem (resident for all steps)
#pragma unroll 4
    for (int i = 0; i < 32; i++) {
        int f = tid + i * 128;
        int kk = f >> 3, c4 = (f & 7) << 2;
        float4 w = *(const float4*)(Wsrc + (long)kk * 512 + c4);
        uint4 u;
        u.x = f2tf(w.x); u.y = f2tf(w.y); u.z = f2tf(w.z); u.w = f2tf(w.w);
        *(uint4*)(Bs + kk * BSTR + c4) = u;
    }

    // static elementwise assignment (4 slots, strided by NTHR)
    const float* b2 = bv + 2 * NG3;   // b[1][0]
    const int tg = ct * 128 + tid;
    int  e_half[4], e_b[4], e_u[4];
    bool e_v[4];
    float e_b2r[4], e_b2z[4], e_b2n[4];
#pragma unroll
    for (int e = 0; e < 4; e++) {
        int it = tg + e * NTHR;
        e_v[e] = (it < EWTOT);
        int ith = e_v[e] ? it : 0;
        e_half[e] = ith >> 15;
        e_b[e]    = (ith >> 9) & 63;
        e_u[e]    = ith & 511;
        if (e_v[e] && e_half[e]) {
            e_b2r[e] = __ldg(b2 + e_u[e]);
            e_b2z[e] = __ldg(b2 + 512 + e_u[e]);
            e_b2n[e] = __ldg(b2 + 1024 + e_u[e]);
        }
    }

    const unsigned as_base = (unsigned)__cvta_generic_to_shared(As);
    __syncthreads();

    for (int k = 0; k <= SS; k++) {
        const int rd = k & 1, wr = rd ^ 1;

        // A-fill: cp.async straight from pre-rounded tf32 h copy
        {
            const float4* hsrc = (const float4*)g_ha[rd][(seg == 2) ? 1 : 0];
#pragma unroll 8
            for (int i = 0; i < 64; i++) {
                cpasync16(as_base + (unsigned)(i * ASTR + tid * 4) * 4u,
                          hsrc + i * 128 + tid);
            }
            cpasync_wait_all();
        }
        __syncthreads();

        // 64x32 tile GEMM, K=512
        float acc[2][2][4];
#pragma unroll
        for (int a = 0; a < 2; a++)
#pragma unroll
            for (int b = 0; b < 2; b++)
#pragma unroll
                for (int c = 0; c < 4; c++) acc[a][b][c] = 0.f;

        const unsigned* ApA = As + (wm * 32 + gq) * ASTR;
        const unsigned* Bp0 = Bs + wn * 16 + gq;
        const unsigned* Bp1 = Bp0 + 8;

#pragma unroll 4
        for (int k8 = 0; k8 < 64; k8++) {
            const int kb = k8 * 8;
            unsigned a0[4], a1[4];
            a0[0] = ApA[kb + tq];
            a0[1] = ApA[8 * ASTR + kb + tq];
            a0[2] = ApA[kb + 4 + tq];
            a0[3] = ApA[8 * ASTR + kb + 4 + tq];
            a1[0] = ApA[16 * ASTR + kb + tq];
            a1[1] = ApA[24 * ASTR + kb + tq];
            a1[2] = ApA[16 * ASTR + kb + 4 + tq];
            a1[3] = ApA[24 * ASTR + kb + 4 + tq];
            unsigned b00 = Bp0[(kb + tq) * BSTR];
            unsigned b01 = Bp0[(kb + 4 + tq) * BSTR];
            unsigned b10 = Bp1[(kb + tq) * BSTR];
            unsigned b11 = Bp1[(kb + 4 + tq) * BSTR];
            mma8(acc[0][0], a0, b00, b01);
            mma8(acc[1][0], a1, b00, b01);
            mma8(acc[0][1], a0, b10, b11);
            mma8(acc[1][1], a1, b10, b11);
        }

        // write G tile (L2 only)
        {
            int colb = ct * 32 + wn * 16;
#pragma unroll
            for (int mf = 0; mf < 2; mf++)
#pragma unroll
                for (int nf = 0; nf < 2; nf++) {
                    int row = wm * 32 + mf * 16 + gq;
                    int col = colb + nf * 8 + tq * 2;
                    __stcg((float2*)(g_G + (long)row * STEPN + col),
                           make_float2(acc[mf][nf][0], acc[mf][nf][1]));
                    __stcg((float2*)(g_G + (long)(row + 8) * STEPN + col),
                           make_float2(acc[mf][nf][2], acc[mf][nf][3]));
                }
        }

        // prefetch G-independent EW operands (latency hidden by barrier wait)
        float pf_xr[4], pf_xz[4], pf_xn[4], pf_hp[4];
#pragma unroll
        for (int e = 0; e < 4; e++) {
            pf_xr[e] = pf_xz[e] = pf_xn[e] = pf_hp[e] = 0.f;
            if (e_v[e]) {
                if (e_half[e] == 0) {
                    if (k < SS) {
                        const float* xs = g_xs1 + ((long)k * BB + e_b[e]) * NG3 + e_u[e];
                        pf_xr[e] = __ldcg(xs);
                        pf_xz[e] = __ldcg(xs + 512);
                        pf_xn[e] = __ldcg(xs + 1024);
                        pf_hp[e] = __ldcg(&g_h[rd][0][e_b[e] * HH + e_u[e]]);
                    }
                } else if (k >= 1) {
                    pf_hp[e] = __ldcg(&g_h[rd][1][e_b[e] * HH + e_u[e]]);
                }
            }
        }

        grid_bar();   // G visible everywhere

        // elementwise GRU updates
#pragma unroll
        for (int e = 0; e < 4; e++) {
            if (!e_v[e]) continue;
            const float* G = g_G + e_b[e] * STEPN;
            const int u = e_u[e];
            const int idx = e_b[e] * HH + u;
            if (e_half[e] == 0) {
                if (k < SS) {
                    float gr = __ldcg(G + u);
                    float gz = __ldcg(G + 512 + u);
                    float gn = __ldcg(G + 1024 + u);
                    float r  = sigm(pf_xr[e] + gr);
                    float z  = sigm(pf_xz[e] + gz);
                    float nn = tanh_fast(pf_xn[e] + r * gn);
                    float v  = (1.f - z) * nn + z * pf_hp[e];
                    __stcg(&g_h[wr][0][idx], v);
                    __stcg(&g_ha[wr][0][idx], __uint_as_float(f2tf(v)));
                }
            } else if (k >= 1) {
                float xr = __ldcg(G + 1536 + u) + e_b2r[e];
                float xz = __ldcg(G + 2048 + u) + e_b2z[e];
                float xn = __ldcg(G + 2560 + u) + e_b2n[e];
                float r2 = sigm(xr + __ldcg(G + 3072 + u));
                float z2 = sigm(xz + __ldcg(G + 3584 + u));
                float n2 = tanh_fast(xn + r2 * __ldcg(G + 4096 + u));
                float v  = (1.f - z2) * n2 + z2 * pf_hp[e];
                __stcg(&g_h[wr][1][idx], v);
                __stcg(&g_ha[wr][1][idx], __uint_as_float(f2tf(v)));
                if (k == SS) __stcg(&g_fcin[e_b[e] * (2 * HH) + u], v);
            }
        }

        grid_bar();   // h visible everywhere before next step
    }
}

// backward step 1 projection: x[:,1023,:] @ Wi[0][1] + b[0][1]
__global__ __launch_bounds__(128) void k_gb1(const float* __restrict__ x,
                                             const float* __restrict__ Wi,
                                             const float* __restrict__ bv)
{
    int n = blockIdx.x * 64;
    int gate = n >> 9, cig = n & 511;
    const float* A = x + (long)(SS - 1) * II;
    const float* B512 = Wi + ((long)(1 * 3 + gate)) * 512 * 512 + cig;   // Wi[0][1]
    gemm_core(A, (long)SS * II, B512, 512, bv + 1 * NG3 + n, g_gb1 + n, NG3);
}

__global__ void k_ewb1()
{
    int b = blockIdx.x, u = threadIdx.x;
    float z  = sigm(g_gb1[b * NG3 + 512 + u]);
    float nn = tanh_fast(g_gb1[b * NG3 + 1024 + u]);
    g_h1b[b * HH + u] = (1.f - z) * nn;
}

// backward step 2 projection: h1b @ Wi[1][1] + b[1][1]
__global__ __launch_bounds__(128) void k_gb2(const float* __restrict__ Wi,
                                             const float* __restrict__ bv)
{
    int n = blockIdx.x * 64;
    int gate = n >> 9, cig = n & 511;
    const float* B512 = Wi + ((long)(3 * 3 + gate)) * 512 * 512 + cig;   // Wi[1][1]
    gemm_core(g_h1b, HH, B512, 512, bv + 3 * NG3 + n, g_gb2 + n, NG3);
}

__global__ void k_ewb2()
{
    int b = blockIdx.x, u = threadIdx.x;
    float z  = sigm(g_gb2[b * NG3 + 512 + u]);
    float nn = tanh_fast(g_gb2[b * NG3 + 1024 + u]);
    g_fcin[b * (2 * HH) + HH + u] = (1.f - z) * nn;
}

// final FC: out[64,512] = fcin[64,1024] @ fc_w + fc_b
__global__ __launch_bounds__(128) void k_fc(const float* __restrict__ fw,
                                            const float* __restrict__ fb,
                                            float* __restrict__ out)
{
    int n = blockIdx.x * 64;
    gemm_core(g_fcin, 2 * HH, fw + n, 2 * HH, fb + n, out + n, HH);
}

// ---------------- launch ------------------------------------------------------
extern "C" void kernel_launch(void* const* d_in, const int* in_sizes, int n_in,
                              void* d_out, int out_size)
{
    const float* x  = (const float*)d_in[0];
    const float* Wi = (const float*)d_in[1];
    const float* Wh = (const float*)d_in[2];
    const float* bv = (const float*)d_in[3];
    const float* fw = (const float*)d_in[4];
    const float* fb = (const float*)d_in[5];
    float* out = (float*)d_out;

    cudaFuncSetAttribute(k_scan, cudaFuncAttributeMaxDynamicSharedMemorySize, SCAN_SMEM);

    k_zero<<<64, 256>>>();

    dim3 gp(NG3 / 64, SS);
    k_proj<<<gp, 128>>>(x, Wi, bv);

    // backward direction: collapses to 2 GRU steps (h0 = 0)
    k_gb1<<<NG3 / 64, 128>>>(x, Wi, bv);
    k_ewb1<<<BB, HH>>>();
    k_gb2<<<NG3 / 64, 128>>>(Wi, bv);
    k_ewb2<<<BB, HH>>>();

    // forward scan: one persistent kernel, 1025 fused steps
    k_scan<<<NCTA, 128, SCAN_SMEM>>>(Wi, Wh, bv);

    k_fc<<<HH / 64, 128>>>(fw, fb, out);
}